// round 8
// baseline (speedup 1.0000x reference)
#include <cuda_runtime.h>
#include <cuda_bf16.h>
#include <cstdint>

// Problem constants
#define NB 2048
#define NQ 128
#define NS 128   // K
#define NH 32    // N (hidden)
#define NC (NQ * NS)

// Interleaved W layout: per h-row, 8 ksteps x 4 F-chunks x 16B.
// chunk(h, ks, F) = [ hi(cols 4F..4F+3) : 8B | lo(same cols) : 8B ]
// Row stride 576B = 144 words; 144 mod 32 = 16 -> adjacent h rows use
// disjoint bank quartets within each 8-lane LDS.128 phase (conflict-free).
#define WROWB 576

// ---- SMEM byte layout ----
#define OFF_W2   0                        // 32 f32
#define OFF_B1   128                      // 32 f32
#define OFF_WHL  256                      // 32*576 = 18432
#define SMEM_TOTAL (OFF_WHL + 32 * WROWB) // 18688

__device__ __forceinline__ void mma16816(float* d, const uint32_t* a, uint32_t b0, uint32_t b1) {
    asm volatile(
        "mma.sync.aligned.m16n8k16.row.col.f32.bf16.bf16.f32 "
        "{%0,%1,%2,%3}, {%4,%5,%6,%7}, {%8,%9}, {%0,%1,%2,%3};"
        : "+f"(d[0]), "+f"(d[1]), "+f"(d[2]), "+f"(d[3])
        : "r"(a[0]), "r"(a[1]), "r"(a[2]), "r"(a[3]), "r"(b0), "r"(b1));
}

// fp32x2 -> (bf16x2 hi, bf16x2 lo) two-term split, packed for mma operands.
__device__ __forceinline__ void cvt_split(float2 v, uint32_t& hi, uint32_t& lo) {
    __nv_bfloat162 h2 = __float22bfloat162_rn(v);
    float2 hf = __bfloat1622float2(h2);
    float2 l;
    l.x = v.x - hf.x;
    l.y = v.y - hf.y;
    __nv_bfloat162 l2 = __float22bfloat162_rn(l);
    hi = *reinterpret_cast<uint32_t*>(&h2);
    lo = *reinterpret_cast<uint32_t*>(&l2);
}

// One kstep: convert current buffer, prefetch ks+2 into the same buffer,
// then B loads (LDS.128, hi+lo fused) and 24 MMAs.
__device__ __forceinline__ void kstep_body(
    int ks, float4 (&v)[2][2], bool pf, const float* __restrict__ xb,
    const char* bBase, float (&acc)[2][4][4])
{
    uint32_t aHi[2][4], aLo[2][4];
#pragma unroll
    for (int mt = 0; mt < 2; mt++)
#pragma unroll
        for (int rh = 0; rh < 2; rh++) {
            float2 p0 = make_float2(v[mt][rh].x, v[mt][rh].y);
            float2 p1 = make_float2(v[mt][rh].z, v[mt][rh].w);
            cvt_split(p0, aHi[mt][rh],     aLo[mt][rh]);      // slots 2F,2F+1
            cvt_split(p1, aHi[mt][2 + rh], aLo[mt][2 + rh]);  // slots 2F+8,2F+9
        }

    if (pf) {
#pragma unroll
        for (int mt = 0; mt < 2; mt++)
#pragma unroll
            for (int rh = 0; rh < 2; rh++)
                v[mt][rh] = __ldcs((const float4*)(xb + mt * 16 * NC + rh * 8 * NC
                                                      + (ks + 2) * 16));
    }

#pragma unroll
    for (int nt = 0; nt < 4; nt++) {
        const uint4 bq = *(const uint4*)(bBase + nt * 8 * WROWB + ks * 64);  // LDS.128
        mma16816(acc[0][nt], aHi[0], bq.x, bq.y);   // xHi * wHi
        mma16816(acc[1][nt], aHi[1], bq.x, bq.y);
        mma16816(acc[0][nt], aHi[0], bq.z, bq.w);   // xHi * wLo
        mma16816(acc[1][nt], aHi[1], bq.z, bq.w);
        mma16816(acc[0][nt], aLo[0], bq.x, bq.y);   // xLo * wHi
        mma16816(acc[1][nt], aLo[1], bq.x, bq.y);
    }
}

__global__ void __launch_bounds__(128, 5)
div_enc_kernel(const float* __restrict__ x, const float* __restrict__ W1,
               const float* __restrict__ b1, const float* __restrict__ W2,
               const float* __restrict__ b2, float* __restrict__ out) {
    extern __shared__ char smem[];
    const int tid  = threadIdx.x;
    const int wid  = tid >> 5;
    const int lane = tid & 31;

    const int q     = blockIdx.x & (NQ - 1);
    const int btile = blockIdx.x >> 7;

    // ---- stage W2 / b1 ----
    if (tid < 32) {
        ((float*)(smem + OFF_W2))[tid] = W2[q * NH + tid];
        ((float*)(smem + OFF_B1))[tid] = b1[q * NH + tid];
    }

    // ---- W1[q] (gmem [s][h]) -> interleaved hi/lo chunks ----
    {
        const float* w1q = W1 + (size_t)q * NS * NH;
        const int h  = tid & 31;
        const int sb = tid >> 5;
#pragma unroll 8
        for (int j = 0; j < 32; j++) {
            const int s = j * 4 + sb;
            float v = w1q[s * NH + h];               // coalesced: h contiguous
            __nv_bfloat16 hi = __float2bfloat16(v);
            __nv_bfloat16 lo = __float2bfloat16(v - __bfloat162float(hi));
            char* p = smem + OFF_WHL + h * WROWB + (s >> 4) * 64
                    + (((s >> 2) & 3) * 16) + ((s & 3) * 2);
            *(__nv_bfloat16*)p       = hi;
            *(__nv_bfloat16*)(p + 8) = lo;
        }
    }
    __syncthreads();

    // ---- mainloop ----
    float acc[2][4][4];
#pragma unroll
    for (int mt = 0; mt < 2; mt++)
#pragma unroll
        for (int nt = 0; nt < 4; nt++)
#pragma unroll
            for (int i = 0; i < 4; i++) acc[mt][nt][i] = 0.f;

    // A load base: row0 = btile*128 + wid*32 + (lane>>2), col = q*NS + (lane&3)*4
    const float* xb = x + (size_t)(btile * 128 + wid * 32 + (lane >> 2)) * NC
                        + (size_t)q * NS + (size_t)((lane & 3) * 4);

    const char* bBase = smem + OFF_WHL + (lane >> 2) * WROWB + (lane & 3) * 16;

    // depth-2 pipeline: preload ksteps 0 and 1 into ping-pong buffers
    float4 v[2][2][2];   // [buf][mt][rh]
#pragma unroll
    for (int b = 0; b < 2; b++)
#pragma unroll
        for (int mt = 0; mt < 2; mt++)
#pragma unroll
            for (int rh = 0; rh < 2; rh++)
                v[b][mt][rh] = __ldcs((const float4*)(xb + mt * 16 * NC + rh * 8 * NC
                                                         + b * 16));

#pragma unroll
    for (int ksp = 0; ksp < 4; ksp++) {
        kstep_body(2 * ksp,     v[0], ksp < 3, xb, bBase, acc);
        kstep_body(2 * ksp + 1, v[1], ksp < 3, xb, bBase, acc);
    }

    // ---- epilogue: +b1, ELU, dot W2, quad-reduce, store ----
    float b1v[4][2], w2v[4][2];
    const float* s_b1 = (const float*)(smem + OFF_B1);
    const float* s_w2 = (const float*)(smem + OFF_W2);
#pragma unroll
    for (int nt = 0; nt < 4; nt++)
#pragma unroll
        for (int i = 0; i < 2; i++) {
            const int h = nt * 8 + (lane & 3) * 2 + i;
            b1v[nt][i] = s_b1[h];
            w2v[nt][i] = s_w2[h];
        }
    const float b2q = b2[q];

#pragma unroll
    for (int mt = 0; mt < 2; mt++) {
        float p0 = 0.f, p1 = 0.f;
#pragma unroll
        for (int nt = 0; nt < 4; nt++) {
#pragma unroll
            for (int i = 0; i < 2; i++) {
                float hv = acc[mt][nt][i] + b1v[nt][i];
                float e  = (hv > 0.f) ? hv : (__expf(hv) - 1.0f);
                p0 = fmaf(e, w2v[nt][i], p0);
                hv = acc[mt][nt][2 + i] + b1v[nt][i];
                e  = (hv > 0.f) ? hv : (__expf(hv) - 1.0f);
                p1 = fmaf(e, w2v[nt][i], p1);
            }
        }
        p0 += __shfl_xor_sync(0xFFFFFFFFu, p0, 1);
        p0 += __shfl_xor_sync(0xFFFFFFFFu, p0, 2);
        p1 += __shfl_xor_sync(0xFFFFFFFFu, p1, 1);
        p1 += __shfl_xor_sync(0xFFFFFFFFu, p1, 2);
        if ((lane & 3) == 0) {
            const int m = btile * 128 + wid * 32 + mt * 16 + (lane >> 2);
            out[(size_t)m * NQ + q]       = p0 + b2q;
            out[(size_t)(m + 8) * NQ + q] = p1 + b2q;
        }
    }
}

extern "C" void kernel_launch(void* const* d_in, const int* in_sizes, int n_in,
                              void* d_out, int out_size) {
    const float* x  = (const float*)d_in[0];
    const float* W1 = (const float*)d_in[1];
    const float* b1 = (const float*)d_in[2];
    const float* W2 = (const float*)d_in[3];
    const float* b2 = (const float*)d_in[4];
    float* out = (float*)d_out;

    cudaFuncSetAttribute(div_enc_kernel, cudaFuncAttributeMaxDynamicSharedMemorySize, SMEM_TOTAL);
    div_enc_kernel<<<(NB / 128) * NQ, 128, SMEM_TOTAL>>>(x, W1, b1, W2, b2, out);
}

// round 9
// speedup vs baseline: 1.0668x; 1.0668x over previous
#include <cuda_runtime.h>
#include <cuda_bf16.h>
#include <cstdint>

// Problem constants
#define NB 2048
#define NQ 128
#define NS 128   // K
#define NH 32    // N (hidden)
#define NC (NQ * NS)

// W layout (R8-style): per h-row (stride 576B), 8 ksteps x 4 F-chunks x 16B:
//   chunk(h, ks, F) = [ hi(cols 4F..4F+3) 8B | lo(same) 8B ]
// 576B = 144 words; 144 mod 32 = 16 -> B-frag LDS.128 phases conflict-free.
#define WROWB 576

// X stage: one kstep-PAIR (32 fp32 cols) per stage, 128 rows x 128B = 16KB.
// Chunk-XOR swizzle: physical chunk = c ^ ((r&1)<<2) -> odd rows use the
// opposite bank half; A-frag LDS.128 phases are conflict-free.
#define XSTAGEB 16384
#define NSTAGES 4

// ---- SMEM byte layout ----
#define OFF_W2   0                         // 32 f32
#define OFF_B1   128                       // 32 f32
#define OFF_W    256                       // 32*576 = 18432
#define OFF_X    (OFF_W + 32 * WROWB)      // 18688
#define SMEM_TOTAL (OFF_X + NSTAGES * XSTAGEB)  // 84224

__device__ __forceinline__ uint32_t smem_u32(const void* p) {
    uint32_t a;
    asm("{ .reg .u64 t; cvta.to.shared.u64 t, %1; cvt.u32.u64 %0, t; }" : "=r"(a) : "l"(p));
    return a;
}

__device__ __forceinline__ void cp_async16(uint32_t dst, const void* src) {
    asm volatile("cp.async.cg.shared.global [%0], [%1], 16;" :: "r"(dst), "l"(src) : "memory");
}
#define CP_COMMIT() asm volatile("cp.async.commit_group;" ::: "memory")
template <int N>
__device__ __forceinline__ void cp_wait() {
    asm volatile("cp.async.wait_group %0;" :: "n"(N) : "memory");
}

__device__ __forceinline__ void mma16816(float* d, const uint32_t* a, uint32_t b0, uint32_t b1) {
    asm volatile(
        "mma.sync.aligned.m16n8k16.row.col.f32.bf16.bf16.f32 "
        "{%0,%1,%2,%3}, {%4,%5,%6,%7}, {%8,%9}, {%0,%1,%2,%3};"
        : "+f"(d[0]), "+f"(d[1]), "+f"(d[2]), "+f"(d[3])
        : "r"(a[0]), "r"(a[1]), "r"(a[2]), "r"(a[3]), "r"(b0), "r"(b1));
}

// fp32x2 -> (bf16x2 hi, bf16x2 lo) two-term split, packed for mma operands.
__device__ __forceinline__ void cvt_split(float2 v, uint32_t& hi, uint32_t& lo) {
    __nv_bfloat162 h2 = __float22bfloat162_rn(v);
    float2 hf = __bfloat1622float2(h2);
    float2 l;
    l.x = v.x - hf.x;
    l.y = v.y - hf.y;
    __nv_bfloat162 l2 = __float22bfloat162_rn(l);
    hi = *reinterpret_cast<uint32_t*>(&h2);
    lo = *reinterpret_cast<uint32_t*>(&l2);
}

// Consume one kstep of one stage: A from smem (LDS.128, swizzled), convert,
// B from W chunks (LDS.128 fused hi/lo), 24 MMAs.
__device__ __forceinline__ void consume_kstep(
    const char* smemc, int pair, int ks2, int wid, int lane, float (&acc)[2][4][4])
{
    const int F = lane & 3;
    const int rq = lane >> 2;                      // 0..7
    const int cxor = (rq & 1) << 2;                // row-parity chunk flip
    const int c = ks2 * 4 + F;
    const char* xst = smemc + OFF_X + pair * XSTAGEB + ((c ^ cxor) * 16);

    uint32_t aHi[2][4], aLo[2][4];
#pragma unroll
    for (int mt = 0; mt < 2; mt++)
#pragma unroll
        for (int rh = 0; rh < 2; rh++) {
            const int r = wid * 32 + rq + mt * 16 + rh * 8;
            const float4 v = *(const float4*)(xst + r * 128);
            cvt_split(make_float2(v.x, v.y), aHi[mt][rh],     aLo[mt][rh]);      // slots 2F,2F+1
            cvt_split(make_float2(v.z, v.w), aHi[mt][2 + rh], aLo[mt][2 + rh]);  // slots 2F+8,2F+9
        }

    const int ks = pair * 2 + ks2;
    const char* bBase = smemc + OFF_W + rq * WROWB + F * 16 + ks * 64;
#pragma unroll
    for (int nt = 0; nt < 4; nt++) {
        const uint4 bq = *(const uint4*)(bBase + nt * 8 * WROWB);   // LDS.128
        mma16816(acc[0][nt], aHi[0], bq.x, bq.y);   // xHi * wHi
        mma16816(acc[1][nt], aHi[1], bq.x, bq.y);
        mma16816(acc[0][nt], aHi[0], bq.z, bq.w);   // xHi * wLo
        mma16816(acc[1][nt], aHi[1], bq.z, bq.w);
        mma16816(acc[0][nt], aLo[0], bq.x, bq.y);   // xLo * wHi
        mma16816(acc[1][nt], aLo[1], bq.x, bq.y);
    }
}

__global__ void __launch_bounds__(128, 4)
div_enc_kernel(const float* __restrict__ x, const float* __restrict__ W1,
               const float* __restrict__ b1, const float* __restrict__ W2,
               const float* __restrict__ b2, float* __restrict__ out) {
    extern __shared__ char smem[];
    const uint32_t sb_u32 = smem_u32(smem);
    const int tid  = threadIdx.x;
    const int wid  = tid >> 5;
    const int lane = tid & 31;

    const int q     = blockIdx.x & (NQ - 1);
    const int btile = blockIdx.x >> 7;

    // ---- issue ALL x-tile cp.async first (4 stages, commit per stage) ----
    {
        const int rr = tid >> 3;     // 0..15 (row within 16-row slab)
        const int cc = tid & 7;      // 0..7  (16B chunk)
        const int pc = cc ^ ((rr & 1) << 2);   // physical chunk (r&1 == rr&1)
        const float* xg = x + (size_t)(btile * 128 + rr) * NC + (size_t)q * NS + cc * 4;
#pragma unroll
        for (int st = 0; st < NSTAGES; st++) {
#pragma unroll
            for (int i = 0; i < 8; i++) {
                const int r = i * 16 + rr;
                cp_async16(sb_u32 + OFF_X + st * XSTAGEB + r * 128 + pc * 16,
                           xg + (size_t)i * 16 * NC + st * 32);
            }
            CP_COMMIT();
        }
    }

    // ---- stage W2 / b1 ----
    if (tid < 32) {
        ((float*)(smem + OFF_W2))[tid] = W2[q * NH + tid];
        ((float*)(smem + OFF_B1))[tid] = b1[q * NH + tid];
    }

    // ---- W1[q] (gmem [s][h]) -> fused hi/lo chunks; STS.32 pair stores ----
    {
        const float* w1q = W1 + (size_t)q * NS * NH;
        const int h  = tid & 31;
        const int sb = tid >> 5;
        char* wrow = smem + OFF_W + h * WROWB;
#pragma unroll 4
        for (int j = 0; j < 16; j++) {
            const int s0 = j * 8 + sb * 2;            // even; pair (s0, s0+1)
            float va = w1q[s0 * NH + h];              // coalesced (h contiguous)
            float vb = w1q[(s0 + 1) * NH + h];
            __nv_bfloat16 ha = __float2bfloat16(va);
            __nv_bfloat16 hb = __float2bfloat16(vb);
            __nv_bfloat16 la = __float2bfloat16(va - __bfloat162float(ha));
            __nv_bfloat16 lb = __float2bfloat16(vb - __bfloat162float(hb));
            char* p = wrow + (s0 >> 4) * 64 + (((s0 >> 2) & 3) * 16) + ((s0 & 3) * 2);
            *(uint32_t*)p = (uint32_t)__bfloat16_as_ushort(ha)
                          | ((uint32_t)__bfloat16_as_ushort(hb) << 16);
            *(uint32_t*)(p + 8) = (uint32_t)__bfloat16_as_ushort(la)
                                | ((uint32_t)__bfloat16_as_ushort(lb) << 16);
        }
    }

    // ---- mainloop: wait per stage, then consume its 2 ksteps ----
    float acc[2][4][4];
#pragma unroll
    for (int mt = 0; mt < 2; mt++)
#pragma unroll
        for (int nt = 0; nt < 4; nt++)
#pragma unroll
            for (int i = 0; i < 4; i++) acc[mt][nt][i] = 0.f;

    cp_wait<3>(); __syncthreads();                 // stage 0 + W visible
    consume_kstep(smem, 0, 0, wid, lane, acc);
    consume_kstep(smem, 0, 1, wid, lane, acc);

    cp_wait<2>(); __syncthreads();
    consume_kstep(smem, 1, 0, wid, lane, acc);
    consume_kstep(smem, 1, 1, wid, lane, acc);

    cp_wait<1>(); __syncthreads();
    consume_kstep(smem, 2, 0, wid, lane, acc);
    consume_kstep(smem, 2, 1, wid, lane, acc);

    cp_wait<0>(); __syncthreads();
    consume_kstep(smem, 3, 0, wid, lane, acc);
    consume_kstep(smem, 3, 1, wid, lane, acc);

    // ---- epilogue: +b1, ELU, dot W2, quad-reduce, store ----
    float b1v[4][2], w2v[4][2];
    const float* s_b1 = (const float*)(smem + OFF_B1);
    const float* s_w2 = (const float*)(smem + OFF_W2);
#pragma unroll
    for (int nt = 0; nt < 4; nt++)
#pragma unroll
        for (int i = 0; i < 2; i++) {
            const int h = nt * 8 + (lane & 3) * 2 + i;
            b1v[nt][i] = s_b1[h];
            w2v[nt][i] = s_w2[h];
        }
    const float b2q = b2[q];

#pragma unroll
    for (int mt = 0; mt < 2; mt++) {
        float p0 = 0.f, p1 = 0.f;
#pragma unroll
        for (int nt = 0; nt < 4; nt++) {
#pragma unroll
            for (int i = 0; i < 2; i++) {
                float hv = acc[mt][nt][i] + b1v[nt][i];
                float e  = (hv > 0.f) ? hv : (__expf(hv) - 1.0f);
                p0 = fmaf(e, w2v[nt][i], p0);
                hv = acc[mt][nt][2 + i] + b1v[nt][i];
                e  = (hv > 0.f) ? hv : (__expf(hv) - 1.0f);
                p1 = fmaf(e, w2v[nt][i], p1);
            }
        }
        p0 += __shfl_xor_sync(0xFFFFFFFFu, p0, 1);
        p0 += __shfl_xor_sync(0xFFFFFFFFu, p0, 2);
        p1 += __shfl_xor_sync(0xFFFFFFFFu, p1, 1);
        p1 += __shfl_xor_sync(0xFFFFFFFFu, p1, 2);
        if ((lane & 3) == 0) {
            const int m = btile * 128 + wid * 32 + mt * 16 + (lane >> 2);
            out[(size_t)m * NQ + q]       = p0 + b2q;
            out[(size_t)(m + 8) * NQ + q] = p1 + b2q;
        }
    }
}

extern "C" void kernel_launch(void* const* d_in, const int* in_sizes, int n_in,
                              void* d_out, int out_size) {
    const float* x  = (const float*)d_in[0];
    const float* W1 = (const float*)d_in[1];
    const float* b1 = (const float*)d_in[2];
    const float* W2 = (const float*)d_in[3];
    const float* b2 = (const float*)d_in[4];
    float* out = (float*)d_out;

    cudaFuncSetAttribute(div_enc_kernel, cudaFuncAttributeMaxDynamicSharedMemorySize, SMEM_TOTAL);
    div_enc_kernel<<<(NB / 128) * NQ, 128, SMEM_TOTAL>>>(x, W1, b1, W2, b2, out);
}

// round 10
// speedup vs baseline: 1.0673x; 1.0005x over previous
#include <cuda_runtime.h>
#include <cuda_bf16.h>
#include <cstdint>

// Problem constants
#define NB 2048
#define NQ 128
#define NS 128   // K
#define NH 32    // N (hidden)
#define NC (NQ * NS)

// W layout: per h-row (stride 576B), 8 ksteps x 4 F-chunks x 16B:
//   chunk(h, ks, F) = [ hi(cols 4F..4F+3) 8B | lo(same) 8B ]
// 576B = 144 words = 16 mod 32 banks -> B-frag LDS.128 phases conflict-free.
#define WROWB 576

// X stage: one kstep-PAIR (32 fp32 cols), 128 rows x 128B = 16KB.
// Chunk-XOR swizzle: physical chunk = c ^ ((row&1)<<2) -> odd rows use the
// opposite 64B half; A-frag LDS.128 phases cover 32 distinct banks.
#define XSTAGEB 16384
#define NSTAGES 2

// ---- SMEM byte layout ----
#define OFF_W2   0                          // 32 f32
#define OFF_B1   128                        // 32 f32
#define OFF_W    256                        // 32*576 = 18432
#define OFF_X    (OFF_W + 32 * WROWB)       // 18688
#define SMEM_TOTAL (OFF_X + NSTAGES * XSTAGEB)   // 51456 -> 4 CTAs/SM

__device__ __forceinline__ uint32_t smem_u32(const void* p) {
    uint32_t a;
    asm("{ .reg .u64 t; cvta.to.shared.u64 t, %1; cvt.u32.u64 %0, t; }" : "=r"(a) : "l"(p));
    return a;
}

__device__ __forceinline__ void cp_async16(uint32_t dst, const void* src) {
    asm volatile("cp.async.cg.shared.global [%0], [%1], 16;" :: "r"(dst), "l"(src) : "memory");
}
#define CP_COMMIT() asm volatile("cp.async.commit_group;" ::: "memory")
template <int N>
__device__ __forceinline__ void cp_wait() {
    asm volatile("cp.async.wait_group %0;" :: "n"(N) : "memory");
}

__device__ __forceinline__ void mma16816(float* d, const uint32_t* a, uint32_t b0, uint32_t b1) {
    asm volatile(
        "mma.sync.aligned.m16n8k16.row.col.f32.bf16.bf16.f32 "
        "{%0,%1,%2,%3}, {%4,%5,%6,%7}, {%8,%9}, {%0,%1,%2,%3};"
        : "+f"(d[0]), "+f"(d[1]), "+f"(d[2]), "+f"(d[3])
        : "r"(a[0]), "r"(a[1]), "r"(a[2]), "r"(a[3]), "r"(b0), "r"(b1));
}

// fp32x2 -> (bf16x2 hi, bf16x2 lo) two-term split, packed for mma operands.
__device__ __forceinline__ void cvt_split(float2 v, uint32_t& hi, uint32_t& lo) {
    __nv_bfloat162 h2 = __float22bfloat162_rn(v);
    float2 hf = __bfloat1622float2(h2);
    float2 l;
    l.x = v.x - hf.x;
    l.y = v.y - hf.y;
    __nv_bfloat162 l2 = __float22bfloat162_rn(l);
    hi = *reinterpret_cast<uint32_t*>(&h2);
    lo = *reinterpret_cast<uint32_t*>(&l2);
}

// Consume one staged kstep-pair: each warp handles 16 rows (wid*16..+15).
__device__ __forceinline__ void consume_pair(
    const char* smemc, int slot, int p, int wid, int lane, float (&acc)[4][4])
{
    const int F  = lane & 3;
    const int rq = lane >> 2;                     // 0..7
    const int cx = (rq & 1) << 2;                 // row-parity chunk flip
    const char* xst = smemc + OFF_X + slot * XSTAGEB + (wid * 16 + rq) * 128;

#pragma unroll
    for (int ks2 = 0; ks2 < 2; ks2++) {
        const int c = (ks2 * 4 + F) ^ cx;
        uint32_t aHi[4], aLo[4];
#pragma unroll
        for (int rh = 0; rh < 2; rh++) {
            const float4 v = *(const float4*)(xst + rh * 8 * 128 + c * 16);  // LDS.128
            cvt_split(make_float2(v.x, v.y), aHi[rh],     aLo[rh]);      // slots 2F,2F+1
            cvt_split(make_float2(v.z, v.w), aHi[2 + rh], aLo[2 + rh]);  // slots 2F+8,2F+9
        }
        const int ks = p * 2 + ks2;
        const char* bBase = smemc + OFF_W + rq * WROWB + F * 16 + ks * 64;
#pragma unroll
        for (int nt = 0; nt < 4; nt++) {
            const uint4 bq = *(const uint4*)(bBase + nt * 8 * WROWB);   // LDS.128
            mma16816(acc[nt], aHi, bq.x, bq.y);   // xHi * wHi
            mma16816(acc[nt], aHi, bq.z, bq.w);   // xHi * wLo
            mma16816(acc[nt], aLo, bq.x, bq.y);   // xLo * wHi
        }
    }
}

__global__ void __launch_bounds__(256, 4)
div_enc_kernel(const float* __restrict__ x, const float* __restrict__ W1,
               const float* __restrict__ b1, const float* __restrict__ W2,
               const float* __restrict__ b2, float* __restrict__ out) {
    extern __shared__ char smem[];
    const uint32_t sb_u32 = smem_u32(smem);
    const int tid  = threadIdx.x;
    const int wid  = tid >> 5;
    const int lane = tid & 31;

    const int q     = blockIdx.x & (NQ - 1);
    const int btile = blockIdx.x >> 7;

    // cp.async mapping: thread -> (row rr=tid>>3 of 32, 16B chunk cc=tid&7),
    // covering rows rr+32i, i=0..3. Full 128B lines consumed per 8-lane group.
    const int rr = tid >> 3;
    const int cc = tid & 7;
    const int pc = cc ^ ((rr & 1) << 2);
    const float* xg = x + (size_t)(btile * 128 + rr) * NC + (size_t)q * NS + cc * 4;
    const uint32_t xdst = sb_u32 + OFF_X + rr * 128 + pc * 16;

    // ---- issue stages 0,1 ----
#pragma unroll
    for (int st = 0; st < 2; st++) {
#pragma unroll
        for (int i = 0; i < 4; i++)
            cp_async16(xdst + st * XSTAGEB + i * 32 * 128,
                       xg + (size_t)i * 32 * NC + st * 32);
        CP_COMMIT();
    }

    // ---- stage W2 / b1 ----
    if (tid < 32) {
        ((float*)(smem + OFF_W2))[tid] = W2[q * NH + tid];
        ((float*)(smem + OFF_B1))[tid] = b1[q * NH + tid];
    }

    // ---- W1[q] (gmem [s][h]) -> fused hi/lo chunks ----
    {
        const float* w1q = W1 + (size_t)q * NS * NH;
        const int h  = tid & 31;
        const int sb = tid >> 5;                  // 0..7
        char* wrow = smem + OFF_W + h * WROWB;
#pragma unroll 4
        for (int j = 0; j < 16; j++) {
            const int s = j * 8 + sb;
            float v = w1q[s * NH + h];            // coalesced (h contiguous)
            __nv_bfloat16 hi = __float2bfloat16(v);
            __nv_bfloat16 lo = __float2bfloat16(v - __bfloat162float(hi));
            char* pch = wrow + (s >> 4) * 64 + (((s >> 2) & 3) * 16) + ((s & 3) * 2);
            *(__nv_bfloat16*)pch       = hi;
            *(__nv_bfloat16*)(pch + 8) = lo;
        }
    }

    float acc[4][4];
#pragma unroll
    for (int nt = 0; nt < 4; nt++)
#pragma unroll
        for (int i = 0; i < 4; i++) acc[nt][i] = 0.f;

    // ---- mainloop: 2-stage ring over 4 kstep-pairs ----
    cp_wait<1>(); __syncthreads();                // stage 0 + W visible
    consume_pair(smem, 0, 0, wid, lane, acc);
    __syncthreads();                              // slot 0 free
#pragma unroll
    for (int i = 0; i < 4; i++)                   // stage 2 -> slot 0
        cp_async16(xdst + 0 * XSTAGEB + i * 32 * 128, xg + (size_t)i * 32 * NC + 2 * 32);
    CP_COMMIT();

    cp_wait<1>(); __syncthreads();                // stage 1 done
    consume_pair(smem, 1, 1, wid, lane, acc);
    __syncthreads();                              // slot 1 free
#pragma unroll
    for (int i = 0; i < 4; i++)                   // stage 3 -> slot 1
        cp_async16(xdst + 1 * XSTAGEB + i * 32 * 128, xg + (size_t)i * 32 * NC + 3 * 32);
    CP_COMMIT();

    cp_wait<1>(); __syncthreads();                // stage 2 done
    consume_pair(smem, 0, 2, wid, lane, acc);

    cp_wait<0>(); __syncthreads();                // stage 3 done
    consume_pair(smem, 1, 3, wid, lane, acc);

    // ---- epilogue: +b1, ELU, dot W2, quad-reduce, store ----
    float b1v[4][2], w2v[4][2];
    const float* s_b1 = (const float*)(smem + OFF_B1);
    const float* s_w2 = (const float*)(smem + OFF_W2);
#pragma unroll
    for (int nt = 0; nt < 4; nt++)
#pragma unroll
        for (int i = 0; i < 2; i++) {
            const int h = nt * 8 + (lane & 3) * 2 + i;
            b1v[nt][i] = s_b1[h];
            w2v[nt][i] = s_w2[h];
        }
    const float b2q = b2[q];

    float p0 = 0.f, p1 = 0.f;
#pragma unroll
    for (int nt = 0; nt < 4; nt++) {
#pragma unroll
        for (int i = 0; i < 2; i++) {
            float hv = acc[nt][i] + b1v[nt][i];
            float e  = (hv > 0.f) ? hv : (__expf(hv) - 1.0f);
            p0 = fmaf(e, w2v[nt][i], p0);
            hv = acc[nt][2 + i] + b1v[nt][i];
            e  = (hv > 0.f) ? hv : (__expf(hv) - 1.0f);
            p1 = fmaf(e, w2v[nt][i], p1);
        }
    }
    p0 += __shfl_xor_sync(0xFFFFFFFFu, p0, 1);
    p0 += __shfl_xor_sync(0xFFFFFFFFu, p0, 2);
    p1 += __shfl_xor_sync(0xFFFFFFFFu, p1, 1);
    p1 += __shfl_xor_sync(0xFFFFFFFFu, p1, 2);
    if ((lane & 3) == 0) {
        const int m = btile * 128 + wid * 16 + (lane >> 2);
        out[(size_t)m * NQ + q]       = p0 + b2q;
        out[(size_t)(m + 8) * NQ + q] = p1 + b2q;
    }
}

extern "C" void kernel_launch(void* const* d_in, const int* in_sizes, int n_in,
                              void* d_out, int out_size) {
    const float* x  = (const float*)d_in[0];
    const float* W1 = (const float*)d_in[1];
    const float* b1 = (const float*)d_in[2];
    const float* W2 = (const float*)d_in[3];
    const float* b2 = (const float*)d_in[4];
    float* out = (float*)d_out;

    cudaFuncSetAttribute(div_enc_kernel, cudaFuncAttributeMaxDynamicSharedMemorySize, SMEM_TOTAL);
    div_enc_kernel<<<(NB / 128) * NQ, 256, SMEM_TOTAL>>>(x, W1, b1, W2, b2, out);
}